// round 2
// baseline (speedup 1.0000x reference)
#include <cuda_runtime.h>
#include <cstdint>
#include <cstddef>

// L1 attention scores: out[b,s,t,h] = -(1/sqrt(D)) * sum_d |q[b,s,h,d] - k[b,t,h,d]|
// B=2, S=2048, H=8, D=32. Output [b,s,t,h] (h innermost).
//
// Strategy: compute-bound on fp32 add throughput. Use Blackwell packed
// add.rn.f32x2 (fma pipe) + 64-bit AND for abs (alu pipe, 2x LOP3) so both
// pipes run in parallel -> ~2x over scalar FADD. Store -k in SMEM so
// diff = q + (-k) is a single packed add.
//
// Tiling: block covers (b, 32 s-rows, 32 t-cols, all 8 heads).
//  - All 8 heads in one block => epilogue stores are contiguous over (t,h):
//    each warp-store covers 128B of output (perfect coalescing).
//  - SMEM tiles stored transposed as [dpair][row] float2 with padded row
//    stride 257 (float2 units) => conflict-free LDS.64 for both q (broadcast
//    over tq) and k (16 distinct rows per half-warp) and conflict-free fill.

namespace {
constexpr int Bc  = 2;
constexpr int Sc  = 2048;
constexpr int Hc  = 8;
constexpr int Dc  = 32;
constexpr int SB  = 32;            // s rows per block
constexpr int TB  = 32;            // t cols per block
constexpr int NDP = Dc / 2;        // 16 d-pairs
constexpr int RST = 257;           // padded row stride in float2 units (rows = 256)
constexpr int SMEM_U64 = 2 * NDP * RST;   // q tile + k tile
}

__global__ void __launch_bounds__(256, 2)
l1attn_kernel(const float* __restrict__ qg_, const float* __restrict__ kg_,
              float* __restrict__ out) {
    extern __shared__ unsigned long long sm[];
    unsigned long long* qs = sm;               // [NDP][RST] float2-as-u64
    unsigned long long* ks = sm + NDP * RST;   // [NDP][RST] (negated k)

    const int tid = threadIdx.x;
    const int b   = blockIdx.z;
    const int s0  = blockIdx.y * SB;
    const int t0  = blockIdx.x * TB;

    // Both tiles are contiguous 32KB chunks in global memory:
    // q[b, s0:s0+32, :, :] and k[b, t0:t0+32, :, :]
    const float2* qg = reinterpret_cast<const float2*>(qg_ + (size_t)(b * Sc + s0) * Hc * Dc);
    const float2* kg = reinterpret_cast<const float2*>(kg_ + (size_t)(b * Sc + t0) * Hc * Dc);

    // Fill: 4096 float2 per tile, 16 per thread. Global float2 index
    // f = row*16 + dp with row = s_local*8 + h. Store transposed [dp][row].
    #pragma unroll
    for (int i = 0; i < (SB * Hc * NDP) / 256; i++) {
        int f  = tid + i * 256;
        int r  = f >> 4;
        int dp = f & 15;
        float2 v = qg[f];
        reinterpret_cast<float2&>(qs[dp * RST + r]) = v;
        float2 w = kg[f];
        w.x = -w.x; w.y = -w.y;
        reinterpret_cast<float2&>(ks[dp * RST + r]) = w;
    }
    __syncthreads();

    // Thread mapping: h = tid&7, tq = (tid>>3)&3, warp sw = tid>>5.
    // Each thread: 4 s-values (sw + 8*ii) x 8 t-values (tq + 4*jj), fixed h.
    const int h  = tid & 7;
    const int tq = (tid >> 3) & 3;
    const int sw = tid >> 5;
    const int qoff = sw * 8 + h;   // + 64*ii
    const int koff = tq * 8 + h;   // + 32*jj

    unsigned long long acc[4][8];
    #pragma unroll
    for (int ii = 0; ii < 4; ii++)
        #pragma unroll
        for (int jj = 0; jj < 8; jj++)
            acc[ii][jj] = 0ull;   // packed (0.0f, 0.0f)

    #pragma unroll 2
    for (int dp = 0; dp < NDP; dp++) {
        unsigned long long q2[4], k2[8];
        const unsigned long long* qrow = qs + dp * RST;
        const unsigned long long* krow = ks + dp * RST;
        #pragma unroll
        for (int ii = 0; ii < 4; ii++) q2[ii] = qrow[qoff + 64 * ii];
        #pragma unroll
        for (int jj = 0; jj < 8; jj++) k2[jj] = krow[koff + 32 * jj];

        #pragma unroll
        for (int ii = 0; ii < 4; ii++) {
            #pragma unroll
            for (int jj = 0; jj < 8; jj++) {
                unsigned long long d2, a;
                // diff = q + (-k)  (packed 2x fp32, fma pipe)
                asm("add.rn.f32x2 %0, %1, %2;" : "=l"(d2) : "l"(q2[ii]), "l"(k2[jj]));
                // |diff| (2x LOP3, alu pipe)
                d2 &= 0x7FFFFFFF7FFFFFFFULL;
                // acc += |diff| (packed, fma pipe)
                asm("add.rn.f32x2 %0, %1, %2;" : "=l"(a) : "l"(acc[ii][jj]), "l"(d2));
                acc[ii][jj] = a;
            }
        }
    }

    // Epilogue: out[((b*S+s)*S + t)*H + h] = -(lo+hi)/sqrt(D)
    const float nscale = -0.17677669529663687f;  // -1/sqrt(32)
    #pragma unroll
    for (int ii = 0; ii < 4; ii++) {
        int s = s0 + sw + 8 * ii;
        size_t rowbase = ((size_t)b * Sc + s) * (size_t)Sc;
        #pragma unroll
        for (int jj = 0; jj < 8; jj++) {
            int t = t0 + tq + 4 * jj;
            float2 a = reinterpret_cast<float2&>(acc[ii][jj]);
            out[(rowbase + t) * Hc + h] = (a.x + a.y) * nscale;
        }
    }
}

extern "C" void kernel_launch(void* const* d_in, const int* in_sizes, int n_in,
                              void* d_out, int out_size) {
    const float* q = (const float*)d_in[0];
    const float* k = (const float*)d_in[1];
    float* out = (float*)d_out;

    const int smem_bytes = SMEM_U64 * (int)sizeof(unsigned long long);  // 65792
    cudaFuncSetAttribute(l1attn_kernel,
                         cudaFuncAttributeMaxDynamicSharedMemorySize, smem_bytes);

    dim3 grid(Sc / TB, Sc / SB, Bc);   // (64, 64, 2)
    l1attn_kernel<<<grid, 256, smem_bytes>>>(q, k, out);
}